// round 16
// baseline (speedup 1.0000x reference)
#include <cuda_runtime.h>
#include <cuda_fp16.h>
#include <cstdint>
#include <cmath>

using h16 = __half;

// ---------------------------------------------------------------------------
// Problem constants
// ---------------------------------------------------------------------------
constexpr int BATCH = 32, NT = 320, LX = 704, CH = 768, TMPL = 128;
constexpr int NS = LX - TMPL;          // 576
constexpr int MQ = BATCH * NT;         // 10240
constexpr int MK = BATCH * NS;         // 18432

constexpr size_t SZ_T  = (size_t)MQ * CH;        // 7,864,320
constexpr size_t SZ_W  = (size_t)CH * CH;        // 589,824
constexpr size_t SZ_X  = (size_t)MK * CH;        // 14,155,776
constexpr size_t SZ_S  = (size_t)BATCH * NT * NS;// 5,898,240
constexpr size_t SZ_R  = (size_t)BATCH * NS;     // 18,432

// fp16 pool: split tensors store hi at O, lo at O+SZ. Single-precision fp16
// tensors (VT/VIT, probs, P) use hi slot only.
constexpr size_t O_T   = 0;
constexpr size_t O_WQ  = O_T   + 2 * SZ_T;
constexpr size_t O_WK  = O_WQ  + 2 * SZ_W;
constexpr size_t O_WV  = O_WK  + 2 * SZ_W;
constexpr size_t O_WO  = O_WV  + 2 * SZ_W;
constexpr size_t O_XS  = O_WO  + 2 * SZ_W;
constexpr size_t O_XIS = O_XS  + 2 * SZ_X;
constexpr size_t O_Q   = O_XIS + 2 * SZ_X;
constexpr size_t O_K   = O_Q   + 2 * SZ_T;
constexpr size_t O_KI  = O_K   + 2 * SZ_X;
constexpr size_t O_VT  = O_KI  + 2 * SZ_X;
constexpr size_t O_VIT = O_VT  + 2 * SZ_X;      // VT/VIT fp16 single, 2*SZ_X apart
constexpr size_t O_SH  = O_VIT + 2 * SZ_X;
constexpr size_t O_SIH = O_SH  + 2 * SZ_S;
constexpr size_t O_P   = O_SIH + 2 * SZ_S;
constexpr size_t BF_TOTAL = O_P + 2 * SZ_T;

// fp32 pool
constexpr size_t F_S  = 0;
constexpr size_t F_SI = F_S  + SZ_S;
constexpr size_t F_U  = F_SI + SZ_S;
constexpr size_t F_S1 = F_U  + SZ_T;
constexpr size_t F_S2 = F_S1 + SZ_R;
constexpr size_t F_TOTAL = F_S2 + SZ_R;

__device__ h16   g_bf[BF_TOTAL];
__device__ float g_f[F_TOTAL];

// ---------------------------------------------------------------------------
// PTX helpers (sm_80-level: legal on the harness's compute_103 PTX target)
// ---------------------------------------------------------------------------
__device__ __forceinline__ uint32_t smem_u32(const void* p) {
    uint32_t a;
    asm("{ .reg .u64 t; cvta.to.shared.u64 t, %1; cvt.u32.u64 %0, t; }"
        : "=r"(a) : "l"(p));
    return a;
}

__device__ __forceinline__ void cp16(uint32_t dst, const void* src, bool pred) {
    int sz = pred ? 16 : 0;
    asm volatile("cp.async.cg.shared.global [%0], [%1], 16, %2;"
                 :: "r"(dst), "l"(src), "r"(sz));
}
#define CP_COMMIT() asm volatile("cp.async.commit_group;" ::: "memory")
#define CP_WAIT(N)  asm volatile("cp.async.wait_group %0;" :: "n"(N) : "memory")

__device__ __forceinline__ void ldm_x4(uint32_t* r, uint32_t addr) {
    asm volatile("ldmatrix.sync.aligned.m8n8.x4.shared.b16 {%0,%1,%2,%3}, [%4];"
                 : "=r"(r[0]), "=r"(r[1]), "=r"(r[2]), "=r"(r[3]) : "r"(addr));
}

__device__ __forceinline__ void mma_f16(float* c, const uint32_t* a, const uint32_t* b) {
    asm volatile(
        "mma.sync.aligned.m16n8k16.row.col.f32.f16.f16.f32 "
        "{%0,%1,%2,%3}, {%4,%5,%6,%7}, {%8,%9}, {%0,%1,%2,%3};"
        : "+f"(c[0]), "+f"(c[1]), "+f"(c[2]), "+f"(c[3])
        : "r"(a[0]), "r"(a[1]), "r"(a[2]), "r"(a[3]), "r"(b[0]), "r"(b[1]));
}

// fp16 split: hi+lo represents x to ~2^-24 relative (fp32 grade)
__device__ __forceinline__ void split2(float x, h16& h, h16& l) {
    h = __float2half_rn(x);
    l = __float2half_rn(x - __half2float(h));
}

// ---------------------------------------------------------------------------
// Split-fp16 HMMA GEMM. C[M,N] = sum_k A[m,k]*B[n,k], K-major fp16.
// BM=128, BN=64, BK=32; 256 threads = 8 warps, warp tile 32x32; 3 CTAs/SM.
// PASSES==3: hi/lo operands, 3 passes (Ah*Bh, Ah*Bl, Al*Bh)  [sign path]
// PASSES==1: hi operands only, single pass                    [value path]
// OUTM 0: Cf = alpha*acc (+Dadd); 1: split hi/lo out; 2: fp16 single out.
// DUAL: after K stages of (A,B), accumulate K2 stages of (A2,B2).
// ZSPLIT: z in [0,64): zz = z&31 indexes batch, z>>5 adds sB2/sC2 offsets.
// ---------------------------------------------------------------------------
constexpr int LDS_ROW   = 40;                       // 80B rows: conflict-free ldmatrix
constexpr int TILE_AB   = 128 * LDS_ROW * 2;        // 10240 bytes (A tile)
constexpr int TILE_BB   = 64  * LDS_ROW * 2;        // 5120 bytes  (B tile)
constexpr int OFF_AL    = TILE_AB;
constexpr int OFF_BH    = 2 * TILE_AB;
constexpr int OFF_BL    = 2 * TILE_AB + TILE_BB;
constexpr int STAGE_B   = 2 * TILE_AB + 2 * TILE_BB;// 30720 bytes
constexpr int SMEM_REQ  = 2 * STAGE_B;              // 61440 bytes (3 CTAs = 180KB/SM)

template<int ROWS>
__device__ __forceinline__ void load_tile_async(const h16* __restrict__ src, uint32_t smbase,
                                                int rowBase, int rlim, int ld, int k0, int tid) {
#pragma unroll
    for (int i = 0; i < ROWS / 64; i++) {
        int chunk = tid + i * 256;
        int row = chunk >> 2, cc = chunk & 3;
        int gr = rowBase + row;
        bool ok = gr < rlim;
        const h16* g = src + (size_t)(ok ? gr : 0) * ld + k0 + cc * 8;
        cp16(smbase + row * (LDS_ROW * 2) + cc * 16, g, ok);
    }
}

template<int OUTM, bool ADDD, bool DUAL, bool ZSPLIT, int PASSES>
__global__ __launch_bounds__(256, 3)
void gemm_mma(const h16* __restrict__ Ah, const h16* __restrict__ Al,
              const h16* __restrict__ Bh, const h16* __restrict__ Bl,
              const h16* __restrict__ A2h, const h16* __restrict__ A2l,
              const h16* __restrict__ B2h, const h16* __restrict__ B2l,
              float* __restrict__ Cf, h16* __restrict__ Chi, h16* __restrict__ Clo,
              const float* __restrict__ Dadd,
              int M, int N, int K, int K2, int lda, int ldb, int ldc,
              long long sA, long long sB, long long sC,
              long long sB2, long long sC2, float alpha)
{
    extern __shared__ char dsm[];
    const uint32_t smb = smem_u32(dsm);

    const int tid    = threadIdx.x;
    const int lane   = tid & 31;
    const int warp_m = (tid >> 5) & 3;
    const int warp_n = tid >> 7;

    const int bz = blockIdx.z;
    const int zz = ZSPLIT ? (bz & 31) : bz;
    const int hb = ZSPLIT ? (bz >> 5) : 0;
    Ah += (size_t)zz * sA;
    Bh += (size_t)zz * sB + (size_t)hb * sB2;
    if (PASSES == 3) {
        Al += (size_t)zz * sA;
        Bl += (size_t)zz * sB + (size_t)hb * sB2;
    }
    if (DUAL) {
        A2h += (size_t)zz * sA;  B2h += (size_t)zz * sB;
        if (PASSES == 3) { A2l += (size_t)zz * sA;  B2l += (size_t)zz * sB; }
    }
    if (OUTM == 0) {
        Cf += (size_t)zz * sC + (size_t)hb * sC2;
        if (ADDD) Dadd += (size_t)zz * sC;
    } else {
        Chi += (size_t)zz * sC + (size_t)hb * sC2;
        if (OUTM == 1) Clo += (size_t)zz * sC + (size_t)hb * sC2;
    }

    const int rowBase = blockIdx.y * 128;
    const int colBase = blockIdx.x * 64;

    const int nst1 = K / 32;
    const int nst  = nst1 + (DUAL ? K2 / 32 : 0);

    float acc[32];
#pragma unroll
    for (int i = 0; i < 32; i++) acc[i] = 0.f;

    const uint32_t a_off = (uint32_t)((warp_m * 32 + (lane & 15)) * (LDS_ROW * 2)
                                      + (((lane >> 4) << 3)) * 2);
    const uint32_t b_off = (uint32_t)((warp_n * 32 + ((lane >> 4) << 3) + (lane & 7)) * (LDS_ROW * 2)
                                      + ((((lane >> 3) & 1) << 3)) * 2);

    auto issue_stage = [&](int s) {
        const h16 *ah, *al, *bh, *bl; int k0;
        if (!DUAL || s < nst1) { ah = Ah;  al = Al;  bh = Bh;  bl = Bl;  k0 = s * 32; }
        else                   { ah = A2h; al = A2l; bh = B2h; bl = B2l; k0 = (s - nst1) * 32; }
        uint32_t st = smb + (s & 1) * STAGE_B;
        load_tile_async<128>(ah, st,          rowBase, M, lda, k0, tid);
        load_tile_async<64 >(bh, st + OFF_BH, colBase, N, ldb, k0, tid);
        if (PASSES == 3) {
            load_tile_async<128>(al, st + OFF_AL, rowBase, M, lda, k0, tid);
            load_tile_async<64 >(bl, st + OFF_BL, colBase, N, ldb, k0, tid);
        }
        CP_COMMIT();
    };

    issue_stage(0);

    for (int s = 0; s < nst; s++) {
        if (s + 1 < nst) { issue_stage(s + 1); CP_WAIT(1); }
        else             { CP_WAIT(0); }
        __syncthreads();

        const uint32_t st = smb + (s & 1) * STAGE_B;
#pragma unroll
        for (int kk = 0; kk < 32; kk += 16) {
            uint32_t Af[2][4], Bhf[2][4];
#pragma unroll
            for (int mi = 0; mi < 2; mi++)
                ldm_x4(Af[mi], st + a_off + (uint32_t)(mi * 16 * (LDS_ROW * 2) + kk * 2));
#pragma unroll
            for (int nip = 0; nip < 2; nip++)
                ldm_x4(Bhf[nip], st + OFF_BH + b_off + (uint32_t)(nip * 16 * (LDS_ROW * 2) + kk * 2));
            // pass hh
#pragma unroll
            for (int mi = 0; mi < 2; mi++)
#pragma unroll
                for (int nip = 0; nip < 2; nip++)
#pragma unroll
                    for (int h = 0; h < 2; h++)
                        mma_f16(acc + (mi * 4 + nip * 2 + h) * 4, Af[mi], Bhf[nip] + h * 2);
            if (PASSES == 3) {
                uint32_t Blf[2][4];
#pragma unroll
                for (int nip = 0; nip < 2; nip++)
                    ldm_x4(Blf[nip], st + OFF_BL + b_off + (uint32_t)(nip * 16 * (LDS_ROW * 2) + kk * 2));
#pragma unroll
                for (int mi = 0; mi < 2; mi++)
#pragma unroll
                    for (int nip = 0; nip < 2; nip++)
#pragma unroll
                        for (int h = 0; h < 2; h++)
                            mma_f16(acc + (mi * 4 + nip * 2 + h) * 4, Af[mi], Blf[nip] + h * 2);
                // A-lo into the Af slot (Ah dead), pass lh
#pragma unroll
                for (int mi = 0; mi < 2; mi++)
                    ldm_x4(Af[mi], st + OFF_AL + a_off + (uint32_t)(mi * 16 * (LDS_ROW * 2) + kk * 2));
#pragma unroll
                for (int mi = 0; mi < 2; mi++)
#pragma unroll
                    for (int nip = 0; nip < 2; nip++)
#pragma unroll
                        for (int h = 0; h < 2; h++)
                            mma_f16(acc + (mi * 4 + nip * 2 + h) * 4, Af[mi], Bhf[nip] + h * 2);
            }
        }
        __syncthreads();
    }

    // Epilogue
#pragma unroll
    for (int mi = 0; mi < 2; mi++) {
#pragma unroll
        for (int ni = 0; ni < 4; ni++) {
            const float* c4 = acc + (mi * 4 + ni) * 4;
            int r = rowBase + warp_m * 32 + mi * 16 + (lane >> 2);
            int c = colBase + warp_n * 32 + ni * 8 + (lane & 3) * 2;
            if (c >= N) continue;
#pragma unroll
            for (int h = 0; h < 2; h++) {
                int rr = r + h * 8;
                if (rr >= M) continue;
                size_t off = (size_t)rr * ldc + c;
                float v0 = c4[h * 2 + 0], v1 = c4[h * 2 + 1];
                if (OUTM == 0) {
                    v0 *= alpha; v1 *= alpha;
                    if (ADDD) {
                        float2 d2 = *reinterpret_cast<const float2*>(Dadd + off);
                        v0 += d2.x; v1 += d2.y;
                    }
                    float2 o; o.x = v0; o.y = v1;
                    *reinterpret_cast<float2*>(Cf + off) = o;
                } else if (OUTM == 1) {
                    h16 h0, l0, h1, l1;
                    split2(v0, h0, l0); split2(v1, h1, l1);
                    *reinterpret_cast<__half2*>(Chi + off) = __half2(h0, h1);
                    *reinterpret_cast<__half2*>(Clo + off) = __half2(l0, l1);
                } else {
                    *reinterpret_cast<__half2*>(Chi + off) = __floats2half2_rn(v0, v1);
                }
            }
        }
    }
}

// ---------------------------------------------------------------------------
// Conversion / elementwise kernels
// ---------------------------------------------------------------------------
__global__ __launch_bounds__(256) void cvt_split(const float* __restrict__ in,
                                                 h16* __restrict__ hi,
                                                 h16* __restrict__ lo, size_t n4) {
    size_t i = (size_t)blockIdx.x * 256 + threadIdx.x;
    if (i >= n4) return;
    float4 v = reinterpret_cast<const float4*>(in)[i];
    h16 h[4], l[4];
    split2(v.x, h[0], l[0]); split2(v.y, h[1], l[1]);
    split2(v.z, h[2], l[2]); split2(v.w, h[3], l[3]);
    reinterpret_cast<__half2*>(hi)[i * 2 + 0] = __half2(h[0], h[1]);
    reinterpret_cast<__half2*>(hi)[i * 2 + 1] = __half2(h[2], h[3]);
    reinterpret_cast<__half2*>(lo)[i * 2 + 0] = __half2(l[0], l[1]);
    reinterpret_cast<__half2*>(lo)[i * 2 + 1] = __half2(l[2], l[3]);
}

// gather rows: dst row r <- src row (r/NS)*LX + TMPL + r%NS, then split
__global__ __launch_bounds__(256) void cvt_gather(const float* __restrict__ in,
                                                  h16* __restrict__ hi,
                                                  h16* __restrict__ lo) {
    size_t i = (size_t)blockIdx.x * 256 + threadIdx.x;
    const size_t n4 = SZ_X / 4;
    if (i >= n4) return;
    size_t e = i * 4;
    int row = (int)(e / CH), col = (int)(e % CH);
    int b = row / NS, n = row - b * NS;
    size_t src = ((size_t)b * LX + TMPL + n) * CH + col;
    float4 v = *reinterpret_cast<const float4*>(in + src);
    h16 h[4], l[4];
    split2(v.x, h[0], l[0]); split2(v.y, h[1], l[1]);
    split2(v.z, h[2], l[2]); split2(v.w, h[3], l[3]);
    reinterpret_cast<__half2*>(hi)[i * 2 + 0] = __half2(h[0], h[1]);
    reinterpret_cast<__half2*>(hi)[i * 2 + 1] = __half2(h[2], h[3]);
    reinterpret_cast<__half2*>(lo)[i * 2 + 0] = __half2(l[0], l[1]);
    reinterpret_cast<__half2*>(lo)[i * 2 + 1] = __half2(l[2], l[3]);
}

// transpose 768x768 weight, split to hi/lo: Wt[d][c] = W[c][d]
__global__ __launch_bounds__(256) void wt_kernel(const float* __restrict__ W,
                                                 h16* __restrict__ hi,
                                                 h16* __restrict__ lo) {
    __shared__ float t[32][33];
    int bx = blockIdx.x * 32, by = blockIdx.y * 32;
    int tx = threadIdx.x & 31, ty = threadIdx.x >> 5;
#pragma unroll
    for (int i = ty; i < 32; i += 8)
        t[i][tx] = W[(size_t)(by + i) * CH + bx + tx];
    __syncthreads();
#pragma unroll
    for (int i = ty; i < 32; i += 8) {
        float v = t[tx][i];
        h16 h, l; split2(v, h, l);
        size_t o = (size_t)(bx + i) * CH + by + tx;
        hi[o] = h; lo[o] = l;
    }
}

// ---------------------------------------------------------------------------
// Block reductions / softmax / ratios / xs / layernorm
// ---------------------------------------------------------------------------
__device__ __forceinline__ float blk_red(float v, bool is_max) {
    __shared__ float red[8];
    int lane = threadIdx.x & 31, w = threadIdx.x >> 5;
#pragma unroll
    for (int o = 16; o; o >>= 1) {
        float u = __shfl_xor_sync(0xffffffffu, v, o);
        v = is_max ? fmaxf(v, u) : v + u;
    }
    if (lane == 0) red[w] = v;
    __syncthreads();
    if (w == 0) {
        v = (lane < 8) ? red[lane] : (is_max ? -3.4e38f : 0.f);
#pragma unroll
        for (int o = 4; o; o >>= 1) {
            float u = __shfl_xor_sync(0xffffffffu, v, o);
            v = is_max ? fmaxf(v, u) : v + u;
        }
        if (lane == 0) red[0] = v;
    }
    __syncthreads();
    v = red[0];
    __syncthreads();
    return v;
}

// softmax: fp32 probs in place + fp16 probs (single precision, for 1-pass PV)
__global__ __launch_bounds__(256) void softmax_kernel(float* __restrict__ S,
                                                      h16* __restrict__ hi) {
    size_t base = (size_t)blockIdx.x * NS;
    __shared__ float buf[NS];
    int tid = threadIdx.x;
    float m = -3.4e38f;
    for (int c = tid; c < NS; c += 256) { float v = S[base + c]; buf[c] = v; m = fmaxf(m, v); }
    m = blk_red(m, true);
    float s = 0.f;
    for (int c = tid; c < NS; c += 256) { float e = __expf(buf[c] - m); buf[c] = e; s += e; }
    s = blk_red(s, false);
    float inv = 1.f / s;
    for (int c = tid; c < NS; c += 256) {
        float p = buf[c] * inv;
        S[base + c] = p;
        hi[base + c] = __float2half_rn(p);
    }
}

// Coalesced sign-count ratios
__global__ __launch_bounds__(128) void ratio_kernel(const float* __restrict__ S,
                                                    const float* __restrict__ Si,
                                                    float* __restrict__ s1,
                                                    float* __restrict__ s2) {
    int b = blockIdx.y;
    int n = blockIdx.x * 128 + threadIdx.x;
    if (n >= NS) return;
    const float* a  = S  + (size_t)b * NT * NS;
    const float* ai = Si + (size_t)b * NT * NS;
    int pos = 0, eq = 0;
#pragma unroll 4
    for (int t = 0; t < NT; t++) {
        float x = a[(size_t)t * NS + n], y = ai[(size_t)t * NS + n];
        pos += (x > y);
        eq  += (x == y);
    }
    float rgb = pos * (1.f / NT), eqr = eq * (1.f / NT);
    int idx = b * NS + n;
    s1[idx] = rgb + eqr;
    s2[idx] = 1.f - rgb;
}

// x_s[key][c] = s1[key]*v[key][c] + s2[key]*vi[key][c], v from fp16 VT (transposed)
__global__ __launch_bounds__(256) void xs_kernel(const h16* __restrict__ VT,
                                                 const h16* __restrict__ VIT,
                                                 const float* __restrict__ s1,
                                                 const float* __restrict__ s2,
                                                 float* __restrict__ out) {
    __shared__ float tv[32][33], tw[32][33];
    int k0 = blockIdx.x * 32, c0 = blockIdx.y * 32;
    int tx = threadIdx.x & 31, ty = threadIdx.x >> 5;
#pragma unroll
    for (int i = ty; i < 32; i += 8) {
        size_t o = (size_t)(c0 + i) * MK + k0 + tx;
        tv[i][tx] = __half2float(VT[o]);
        tw[i][tx] = __half2float(VIT[o]);
    }
    __syncthreads();
#pragma unroll
    for (int i = ty; i < 32; i += 8) {
        int key = k0 + i;
        float a = s1[key], b = s2[key];
        out[(size_t)key * CH + c0 + tx] = a * tv[tx][i] + b * tw[tx][i];
    }
}

__global__ __launch_bounds__(256) void ln_kernel(const float* __restrict__ U,
                                                 const float* __restrict__ gamma,
                                                 const float* __restrict__ beta,
                                                 float* __restrict__ out) {
    size_t base = (size_t)blockIdx.x * CH;
    __shared__ float buf[CH];
    int tid = threadIdx.x;
    float s = 0.f;
    for (int c = tid; c < CH; c += 256) { float v = U[base + c]; buf[c] = v; s += v; }
    s = blk_red(s, false);
    float mu = s * (1.f / CH);
    float vs = 0.f;
    for (int c = tid; c < CH; c += 256) { float d = buf[c] - mu; vs += d * d; }
    vs = blk_red(vs, false);
    float inv = rsqrtf(vs * (1.f / CH) + 1e-5f);
    for (int c = tid; c < CH; c += 256)
        out[base + c] = (buf[c] - mu) * inv * gamma[c] + beta[c];
}

// ---------------------------------------------------------------------------
// Launcher. ncu captures the 4th launch (0-based index 3) — keep the big
// K/KI projection GEMM there to track the sign-path GEMM round over round.
// ---------------------------------------------------------------------------
extern "C" void kernel_launch(void* const* d_in, const int* in_sizes, int n_in,
                              void* d_out, int out_size) {
    const float* T     = (const float*)d_in[0];
    const float* x     = (const float*)d_in[1];
    const float* xi    = (const float*)d_in[2];
    const float* Wq    = (const float*)d_in[3];
    const float* Wk    = (const float*)d_in[4];
    const float* Wv    = (const float*)d_in[5];
    const float* Wout  = (const float*)d_in[6];
    const float* gamma = (const float*)d_in[7];
    const float* beta  = (const float*)d_in[8];
    float* out = (float*)d_out;

    void* bp = nullptr; cudaGetSymbolAddress(&bp, g_bf);
    void* fp = nullptr; cudaGetSymbolAddress(&fp, g_f);
    h16*   B = (h16*)bp;
    float* F = (float*)fp;

    cudaFuncSetAttribute(gemm_mma<1, false, false, false, 3>, cudaFuncAttributeMaxDynamicSharedMemorySize, SMEM_REQ);
    cudaFuncSetAttribute(gemm_mma<2, false, false, false, 1>, cudaFuncAttributeMaxDynamicSharedMemorySize, SMEM_REQ);
    cudaFuncSetAttribute(gemm_mma<0, false, false, true,  3>, cudaFuncAttributeMaxDynamicSharedMemorySize, SMEM_REQ);
    cudaFuncSetAttribute(gemm_mma<2, false, true,  false, 1>, cudaFuncAttributeMaxDynamicSharedMemorySize, SMEM_REQ);
    cudaFuncSetAttribute(gemm_mma<0, true,  false, false, 1>, cudaFuncAttributeMaxDynamicSharedMemorySize, SMEM_REQ);

    const float scale = 1.0f / sqrtf((float)CH);
    auto grid = [](int M, int N, int Z) {
        return dim3((unsigned)((N + 63) / 64), (unsigned)((M + 127) / 128), (unsigned)Z);
    };
    dim3 wt_g(CH / 32, CH / 32);

    // --- launches 1-3: minimal deps for the profiled GEMM ---
    wt_kernel<<<wt_g, 256>>>(Wk, B + O_WK, B + O_WK + SZ_W);                          // 1
    cvt_gather<<<(unsigned)(SZ_X / 4 / 256), 256>>>(x,  B + O_XS,  B + O_XS  + SZ_X); // 2
    cvt_gather<<<(unsigned)(SZ_X / 4 / 256), 256>>>(xi, B + O_XIS, B + O_XIS + SZ_X); // 3

    // --- launch 4 (PROFILED): K + KI projections (sign path, 3-pass) ---
    gemm_mma<1, false, false, false, 3><<<grid(MK, CH, 2), 256, SMEM_REQ>>>(
        B + O_XS, B + O_XS + SZ_X, B + O_WK, B + O_WK + SZ_W,
        nullptr, nullptr, nullptr, nullptr,
        nullptr, B + O_K, B + O_K + SZ_X, nullptr,
        MK, CH, CH, 0, CH, CH, CH,
        (long long)(2 * SZ_X), 0, (long long)(2 * SZ_X), 0, 0, 1.f);

    // remaining converts + weight transposes
    wt_kernel<<<wt_g, 256>>>(Wq,   B + O_WQ, B + O_WQ + SZ_W);
    wt_kernel<<<wt_g, 256>>>(Wv,   B + O_WV, B + O_WV + SZ_W);
    wt_kernel<<<wt_g, 256>>>(Wout, B + O_WO, B + O_WO + SZ_W);
    cvt_split<<<(unsigned)(SZ_T / 4 / 256), 256>>>(T, B + O_T, B + O_T + SZ_T, SZ_T / 4);

    // Q = T @ Wq (sign path, 3-pass, split out)
    gemm_mma<1, false, false, false, 3><<<grid(MQ, CH, 1), 256, SMEM_REQ>>>(
        B + O_T, B + O_T + SZ_T, B + O_WQ, B + O_WQ + SZ_W,
        nullptr, nullptr, nullptr, nullptr,
        nullptr, B + O_Q, B + O_Q + SZ_T, nullptr,
        MQ, CH, CH, 0, CH, CH, CH, 0, 0, 0, 0, 0, 1.f);

    // VT / VIT (value path, 1-pass fp16): VT[c][key] = sum_k WvT[c,k]*xs[key,k]
    gemm_mma<2, false, false, false, 1><<<grid(CH, MK, 2), 256, SMEM_REQ>>>(
        B + O_WV, nullptr, B + O_XS, nullptr,
        nullptr, nullptr, nullptr, nullptr,
        nullptr, B + O_VT, nullptr, nullptr,
        CH, MK, CH, 0, CH, CH, MK,
        0, (long long)(2 * SZ_X), (long long)(2 * SZ_X), 0, 0, 1.f);

    // logits (sign path, 3-pass): z in [0,64), zz=z&31 batch, z>=32 -> KI/SI
    gemm_mma<0, false, false, true, 3><<<grid(NT, NS, 64), 256, SMEM_REQ>>>(
        B + O_Q, B + O_Q + SZ_T, B + O_K, B + O_K + SZ_X,
        nullptr, nullptr, nullptr, nullptr,
        F + F_S, nullptr, nullptr, nullptr,
        NT, NS, CH, 0, CH, CH, NS,
        (long long)NT * CH, (long long)NS * CH, (long long)NT * NS,
        (long long)(2 * SZ_X), (long long)SZ_S, scale);

    // softmax: fp32 probs in place + fp16 probs
    softmax_kernel<<<MQ, 256>>>(F + F_S,  B + O_SH);
    softmax_kernel<<<MQ, 256>>>(F + F_SI, B + O_SIH);

    // ratios (coalesced) + x_s
    ratio_kernel<<<dim3((NS + 127) / 128, BATCH), 128>>>(F + F_S, F + F_SI, F + F_S1, F + F_S2);
    xs_kernel<<<dim3(MK / 32, CH / 32), 256>>>(
        B + O_VT, B + O_VIT, F + F_S1, F + F_S2, out);

    // P = aw @ v + awi @ vi (value path, DUAL 1-pass, fp16 out)
    gemm_mma<2, false, true, false, 1><<<grid(NT, CH, BATCH), 256, SMEM_REQ>>>(
        B + O_SH,  nullptr, B + O_VT,  nullptr,
        B + O_SIH, nullptr, B + O_VIT, nullptr,
        nullptr, B + O_P, nullptr, nullptr,
        NT, CH, NS, NS, NS, MK, CH,
        (long long)NT * NS, (long long)NS, (long long)NT * CH, 0, 0, 1.f);

    // U = P @ Wout + T (value path, 1-pass)
    gemm_mma<0, true, false, false, 1><<<grid(MQ, CH, 1), 256, SMEM_REQ>>>(
        B + O_P, nullptr, B + O_WO, nullptr,
        nullptr, nullptr, nullptr, nullptr,
        F + F_U, nullptr, nullptr, T,
        MQ, CH, CH, 0, CH, CH, CH, 0, 0, 0, 0, 0, 1.f);

    // T_new = LayerNorm(U)
    ln_kernel<<<MQ, 256>>>(F + F_U, gamma, beta, out + SZ_X);
}

// round 17
// speedup vs baseline: 1.7095x; 1.7095x over previous
#include <cuda_runtime.h>
#include <cuda_fp16.h>
#include <cuda_bf16.h>
#include <cstdint>
#include <cmath>

using u16  = uint16_t;
using bf16 = __nv_bfloat16;

// ---------------------------------------------------------------------------
// Problem constants
// ---------------------------------------------------------------------------
constexpr int BATCH = 32, NT = 320, LX = 704, CH = 768, TMPL = 128;
constexpr int NS = LX - TMPL;          // 576
constexpr int MQ = BATCH * NT;         // 10240
constexpr int MK = BATCH * NS;         // 18432

constexpr size_t SZ_T  = (size_t)MQ * CH;
constexpr size_t SZ_W  = (size_t)CH * CH;
constexpr size_t SZ_X  = (size_t)MK * CH;
constexpr size_t SZ_S  = (size_t)BATCH * NT * NS;
constexpr size_t SZ_R  = (size_t)BATCH * NS;

// u16 pool. bf16-split tensors: hi at O, lo at O+SZ; siblings 2*SZ apart.
// fp16 singles: siblings SZ apart.
constexpr size_t O_T    = 0;                       // bf16 split (T)
constexpr size_t O_WQ   = O_T    + 2 * SZ_T;       // bf16 split
constexpr size_t O_WK   = O_WQ   + 2 * SZ_W;       // bf16 split
constexpr size_t O_WVF  = O_WK   + 2 * SZ_W;       // fp16 single
constexpr size_t O_WOF  = O_WVF  + SZ_W;           // fp16 single
constexpr size_t O_XS   = O_WOF  + SZ_W;           // bf16 split
constexpr size_t O_XIS  = O_XS   + 2 * SZ_X;       // bf16 split
constexpr size_t O_XSF  = O_XIS  + 2 * SZ_X;       // fp16 single
constexpr size_t O_XISF = O_XSF  + SZ_X;           // fp16 single
constexpr size_t O_Q    = O_XISF + SZ_X;           // bf16 split
constexpr size_t O_K    = O_Q    + 2 * SZ_T;       // bf16 split
constexpr size_t O_KI   = O_K    + 2 * SZ_X;       // bf16 split
constexpr size_t O_VT   = O_KI   + 2 * SZ_X;       // fp16 single
constexpr size_t O_VIT  = O_VT   + SZ_X;           // fp16 single
constexpr size_t O_SHF  = O_VIT  + SZ_X;           // fp16 probs
constexpr size_t O_SIHF = O_SHF  + SZ_S;           // fp16 probs
constexpr size_t O_PF   = O_SIHF + SZ_S;           // fp16 single
constexpr size_t U_TOTAL = O_PF + SZ_T;

// fp32 pool
constexpr size_t F_S  = 0;
constexpr size_t F_SI = F_S  + SZ_S;
constexpr size_t F_U  = F_SI + SZ_S;
constexpr size_t F_S1 = F_U  + SZ_T;
constexpr size_t F_S2 = F_S1 + SZ_R;
constexpr size_t F_TOTAL = F_S2 + SZ_R;

__device__ u16   g_u[U_TOTAL];
__device__ float g_f[F_TOTAL];

// ---------------------------------------------------------------------------
// PTX helpers (sm_80-level: legal on the harness's compute_103 PTX target)
// ---------------------------------------------------------------------------
__device__ __forceinline__ uint32_t smem_u32(const void* p) {
    uint32_t a;
    asm("{ .reg .u64 t; cvta.to.shared.u64 t, %1; cvt.u32.u64 %0, t; }"
        : "=r"(a) : "l"(p));
    return a;
}

__device__ __forceinline__ void cp16(uint32_t dst, const void* src, bool pred) {
    int sz = pred ? 16 : 0;
    asm volatile("cp.async.cg.shared.global [%0], [%1], 16, %2;"
                 :: "r"(dst), "l"(src), "r"(sz));
}
#define CP_COMMIT() asm volatile("cp.async.commit_group;" ::: "memory")
#define CP_WAIT(N)  asm volatile("cp.async.wait_group %0;" :: "n"(N) : "memory")

__device__ __forceinline__ void ldm_x4(uint32_t* r, uint32_t addr) {
    asm volatile("ldmatrix.sync.aligned.m8n8.x4.shared.b16 {%0,%1,%2,%3}, [%4];"
                 : "=r"(r[0]), "=r"(r[1]), "=r"(r[2]), "=r"(r[3]) : "r"(addr));
}

template<bool FP16>
__device__ __forceinline__ void mma16(float* c, const uint32_t* a, const uint32_t* b) {
    if (FP16)
        asm volatile(
            "mma.sync.aligned.m16n8k16.row.col.f32.f16.f16.f32 "
            "{%0,%1,%2,%3}, {%4,%5,%6,%7}, {%8,%9}, {%0,%1,%2,%3};"
            : "+f"(c[0]), "+f"(c[1]), "+f"(c[2]), "+f"(c[3])
            : "r"(a[0]), "r"(a[1]), "r"(a[2]), "r"(a[3]), "r"(b[0]), "r"(b[1]));
    else
        asm volatile(
            "mma.sync.aligned.m16n8k16.row.col.f32.bf16.bf16.f32 "
            "{%0,%1,%2,%3}, {%4,%5,%6,%7}, {%8,%9}, {%0,%1,%2,%3};"
            : "+f"(c[0]), "+f"(c[1]), "+f"(c[2]), "+f"(c[3])
            : "r"(a[0]), "r"(a[1]), "r"(a[2]), "r"(a[3]), "r"(b[0]), "r"(b[1]));
}

__device__ __forceinline__ void split2b(float x, bf16& h, bf16& l) {
    h = __float2bfloat16(x);
    l = __float2bfloat16(x - __bfloat162float(h));
}

// ---------------------------------------------------------------------------
// HMMA GEMM. C[M,N] = sum_k A[m,k]*B[n,k], K-major 16-bit operands.
// BM=128, BN=64, BK=32; 256 threads = 8 warps, warp tile 32x32; 3 CTAs/SM.
// PASSES==3: bf16 hi/lo, 3 passes (Ah*Bh, Ah*Bl, Al*Bh)   [sign path]
// PASSES==1: single operands, 1 pass                       [value path, FP16]
// OUTM 0: Cf = alpha*acc (+Dadd); 1: bf16 hi/lo out; 2: fp16 single out.
// DUAL: after K stages of (A,B), accumulate K2 stages of (A2,B2).
// ZSPLIT: z in [0,64): zz = z&31 indexes batch, z>>5 adds sB2/sC2 offsets.
// ---------------------------------------------------------------------------
constexpr int LDS_ROW   = 40;                       // 80B rows: conflict-free ldmatrix
constexpr int TILE_AB   = 128 * LDS_ROW * 2;        // 10240 bytes
constexpr int TILE_BB   = 64  * LDS_ROW * 2;        // 5120 bytes
constexpr int OFF_AL    = TILE_AB;
constexpr int OFF_BH    = 2 * TILE_AB;
constexpr int OFF_BL    = 2 * TILE_AB + TILE_BB;
constexpr int STAGE_B   = 2 * TILE_AB + 2 * TILE_BB;// 30720 bytes
constexpr int SMEM_REQ  = 2 * STAGE_B;              // 61440 bytes (3 CTAs = 180KB/SM)

template<int ROWS>
__device__ __forceinline__ void load_tile_async(const u16* __restrict__ src, uint32_t smbase,
                                                int rowBase, int rlim, int ld, int k0, int tid) {
#pragma unroll
    for (int i = 0; i < ROWS / 64; i++) {
        int chunk = tid + i * 256;
        int row = chunk >> 2, cc = chunk & 3;
        int gr = rowBase + row;
        bool ok = gr < rlim;
        const u16* g = src + (size_t)(ok ? gr : 0) * ld + k0 + cc * 8;
        cp16(smbase + row * (LDS_ROW * 2) + cc * 16, g, ok);
    }
}

template<int OUTM, bool ADDD, bool DUAL, bool ZSPLIT, int PASSES, bool FP16>
__global__ __launch_bounds__(256, 3)
void gemm_mma(const u16* __restrict__ Ah, const u16* __restrict__ Al,
              const u16* __restrict__ Bh, const u16* __restrict__ Bl,
              const u16* __restrict__ A2h, const u16* __restrict__ A2l,
              const u16* __restrict__ B2h, const u16* __restrict__ B2l,
              float* __restrict__ Cf, u16* __restrict__ Chi, u16* __restrict__ Clo,
              const float* __restrict__ Dadd,
              int M, int N, int K, int K2, int lda, int ldb, int ldc,
              long long sA, long long sB, long long sC,
              long long sB2, long long sC2, float alpha)
{
    extern __shared__ char dsm[];
    const uint32_t smb = smem_u32(dsm);

    const int tid    = threadIdx.x;
    const int lane   = tid & 31;
    const int warp_m = (tid >> 5) & 3;
    const int warp_n = tid >> 7;

    const int bz = blockIdx.z;
    const int zz = ZSPLIT ? (bz & 31) : bz;
    const int hb = ZSPLIT ? (bz >> 5) : 0;
    Ah += (size_t)zz * sA;
    Bh += (size_t)zz * sB + (size_t)hb * sB2;
    if (PASSES == 3) {
        Al += (size_t)zz * sA;
        Bl += (size_t)zz * sB + (size_t)hb * sB2;
    }
    if (DUAL) {
        A2h += (size_t)zz * sA;  B2h += (size_t)zz * sB;
        if (PASSES == 3) { A2l += (size_t)zz * sA;  B2l += (size_t)zz * sB; }
    }
    if (OUTM == 0) {
        Cf += (size_t)zz * sC + (size_t)hb * sC2;
        if (ADDD) Dadd += (size_t)zz * sC;
    } else {
        Chi += (size_t)zz * sC + (size_t)hb * sC2;
        if (OUTM == 1) Clo += (size_t)zz * sC + (size_t)hb * sC2;
    }

    const int rowBase = blockIdx.y * 128;
    const int colBase = blockIdx.x * 64;

    const int nst1 = K / 32;
    const int nst  = nst1 + (DUAL ? K2 / 32 : 0);

    float acc[32];
#pragma unroll
    for (int i = 0; i < 32; i++) acc[i] = 0.f;

    const uint32_t a_off = (uint32_t)((warp_m * 32 + (lane & 15)) * (LDS_ROW * 2)
                                      + (((lane >> 4) << 3)) * 2);
    const uint32_t b_off = (uint32_t)((warp_n * 32 + ((lane >> 4) << 3) + (lane & 7)) * (LDS_ROW * 2)
                                      + ((((lane >> 3) & 1) << 3)) * 2);

    auto issue_stage = [&](int s) {
        const u16 *ah, *al, *bh, *bl; int k0;
        if (!DUAL || s < nst1) { ah = Ah;  al = Al;  bh = Bh;  bl = Bl;  k0 = s * 32; }
        else                   { ah = A2h; al = A2l; bh = B2h; bl = B2l; k0 = (s - nst1) * 32; }
        uint32_t st = smb + (s & 1) * STAGE_B;
        load_tile_async<128>(ah, st,          rowBase, M, lda, k0, tid);
        load_tile_async<64 >(bh, st + OFF_BH, colBase, N, ldb, k0, tid);
        if (PASSES == 3) {
            load_tile_async<128>(al, st + OFF_AL, rowBase, M, lda, k0, tid);
            load_tile_async<64 >(bl, st + OFF_BL, colBase, N, ldb, k0, tid);
        }
        CP_COMMIT();
    };

    issue_stage(0);

    for (int s = 0; s < nst; s++) {
        if (s + 1 < nst) { issue_stage(s + 1); CP_WAIT(1); }
        else             { CP_WAIT(0); }
        __syncthreads();

        const uint32_t st = smb + (s & 1) * STAGE_B;
#pragma unroll
        for (int kk = 0; kk < 32; kk += 16) {
            uint32_t Af[2][4], Bhf[2][4];
#pragma unroll
            for (int mi = 0; mi < 2; mi++)
                ldm_x4(Af[mi], st + a_off + (uint32_t)(mi * 16 * (LDS_ROW * 2) + kk * 2));
#pragma unroll
            for (int nip = 0; nip < 2; nip++)
                ldm_x4(Bhf[nip], st + OFF_BH + b_off + (uint32_t)(nip * 16 * (LDS_ROW * 2) + kk * 2));
            // pass hh
#pragma unroll
            for (int mi = 0; mi < 2; mi++)
#pragma unroll
                for (int nip = 0; nip < 2; nip++)
#pragma unroll
                    for (int h = 0; h < 2; h++)
                        mma16<FP16>(acc + (mi * 4 + nip * 2 + h) * 4, Af[mi], Bhf[nip] + h * 2);
            if (PASSES == 3) {
                uint32_t Blf[2][4];
#pragma unroll
                for (int nip = 0; nip < 2; nip++)
                    ldm_x4(Blf[nip], st + OFF_BL + b_off + (uint32_t)(nip * 16 * (LDS_ROW * 2) + kk * 2));
#pragma unroll
                for (int mi = 0; mi < 2; mi++)
#pragma unroll
                    for (int nip = 0; nip < 2; nip++)
#pragma unroll
                        for (int h = 0; h < 2; h++)
                            mma16<FP16>(acc + (mi * 4 + nip * 2 + h) * 4, Af[mi], Blf[nip] + h * 2);
                // A-lo into the Af slot (Ah dead), pass lh
#pragma unroll
                for (int mi = 0; mi < 2; mi++)
                    ldm_x4(Af[mi], st + OFF_AL + a_off + (uint32_t)(mi * 16 * (LDS_ROW * 2) + kk * 2));
#pragma unroll
                for (int mi = 0; mi < 2; mi++)
#pragma unroll
                    for (int nip = 0; nip < 2; nip++)
#pragma unroll
                        for (int h = 0; h < 2; h++)
                            mma16<FP16>(acc + (mi * 4 + nip * 2 + h) * 4, Af[mi], Bhf[nip] + h * 2);
            }
        }
        __syncthreads();
    }

    // Epilogue
#pragma unroll
    for (int mi = 0; mi < 2; mi++) {
#pragma unroll
        for (int ni = 0; ni < 4; ni++) {
            const float* c4 = acc + (mi * 4 + ni) * 4;
            int r = rowBase + warp_m * 32 + mi * 16 + (lane >> 2);
            int c = colBase + warp_n * 32 + ni * 8 + (lane & 3) * 2;
            if (c >= N) continue;
#pragma unroll
            for (int h = 0; h < 2; h++) {
                int rr = r + h * 8;
                if (rr >= M) continue;
                size_t off = (size_t)rr * ldc + c;
                float v0 = c4[h * 2 + 0], v1 = c4[h * 2 + 1];
                if (OUTM == 0) {
                    v0 *= alpha; v1 *= alpha;
                    if (ADDD) {
                        float2 d2 = *reinterpret_cast<const float2*>(Dadd + off);
                        v0 += d2.x; v1 += d2.y;
                    }
                    float2 o; o.x = v0; o.y = v1;
                    *reinterpret_cast<float2*>(Cf + off) = o;
                } else if (OUTM == 1) {
                    bf16 h0, l0, h1, l1;
                    split2b(v0, h0, l0); split2b(v1, h1, l1);
                    *reinterpret_cast<__nv_bfloat162*>(Chi + off) = __nv_bfloat162(h0, h1);
                    *reinterpret_cast<__nv_bfloat162*>(Clo + off) = __nv_bfloat162(l0, l1);
                } else {
                    *reinterpret_cast<__half2*>(Chi + off) = __floats2half2_rn(v0, v1);
                }
            }
        }
    }
}

// ---------------------------------------------------------------------------
// Conversion / elementwise kernels
// ---------------------------------------------------------------------------
__global__ __launch_bounds__(256) void cvt_split(const float* __restrict__ in,
                                                 u16* __restrict__ hi,
                                                 u16* __restrict__ lo, size_t n4) {
    size_t i = (size_t)blockIdx.x * 256 + threadIdx.x;
    if (i >= n4) return;
    float4 v = reinterpret_cast<const float4*>(in)[i];
    bf16 h[4], l[4];
    split2b(v.x, h[0], l[0]); split2b(v.y, h[1], l[1]);
    split2b(v.z, h[2], l[2]); split2b(v.w, h[3], l[3]);
    reinterpret_cast<__nv_bfloat162*>(hi)[i * 2 + 0] = __nv_bfloat162(h[0], h[1]);
    reinterpret_cast<__nv_bfloat162*>(hi)[i * 2 + 1] = __nv_bfloat162(h[2], h[3]);
    reinterpret_cast<__nv_bfloat162*>(lo)[i * 2 + 0] = __nv_bfloat162(l[0], l[1]);
    reinterpret_cast<__nv_bfloat162*>(lo)[i * 2 + 1] = __nv_bfloat162(l[2], l[3]);
}

// gather rows (dst r <- src (r/NS)*LX + TMPL + r%NS), emit bf16 hi/lo + fp16
__global__ __launch_bounds__(256) void cvt_gather3(const float* __restrict__ in,
                                                   u16* __restrict__ hi,
                                                   u16* __restrict__ lo,
                                                   u16* __restrict__ f) {
    size_t i = (size_t)blockIdx.x * 256 + threadIdx.x;
    const size_t n4 = SZ_X / 4;
    if (i >= n4) return;
    size_t e = i * 4;
    int row = (int)(e / CH), col = (int)(e % CH);
    int b = row / NS, n = row - b * NS;
    size_t src = ((size_t)b * LX + TMPL + n) * CH + col;
    float4 v = *reinterpret_cast<const float4*>(in + src);
    bf16 h[4], l[4];
    split2b(v.x, h[0], l[0]); split2b(v.y, h[1], l[1]);
    split2b(v.z, h[2], l[2]); split2b(v.w, h[3], l[3]);
    reinterpret_cast<__nv_bfloat162*>(hi)[i * 2 + 0] = __nv_bfloat162(h[0], h[1]);
    reinterpret_cast<__nv_bfloat162*>(hi)[i * 2 + 1] = __nv_bfloat162(h[2], h[3]);
    reinterpret_cast<__nv_bfloat162*>(lo)[i * 2 + 0] = __nv_bfloat162(l[0], l[1]);
    reinterpret_cast<__nv_bfloat162*>(lo)[i * 2 + 1] = __nv_bfloat162(l[2], l[3]);
    reinterpret_cast<__half2*>(f)[i * 2 + 0] = __floats2half2_rn(v.x, v.y);
    reinterpret_cast<__half2*>(f)[i * 2 + 1] = __floats2half2_rn(v.z, v.w);
}

// transpose 768x768 weight, bf16 split: Wt[d][c] = W[c][d]
__global__ __launch_bounds__(256) void wt_bf(const float* __restrict__ W,
                                             u16* __restrict__ hi,
                                             u16* __restrict__ lo) {
    __shared__ float t[32][33];
    int bx = blockIdx.x * 32, by = blockIdx.y * 32;
    int tx = threadIdx.x & 31, ty = threadIdx.x >> 5;
#pragma unroll
    for (int i = ty; i < 32; i += 8)
        t[i][tx] = W[(size_t)(by + i) * CH + bx + tx];
    __syncthreads();
#pragma unroll
    for (int i = ty; i < 32; i += 8) {
        float v = t[tx][i];
        bf16 h, l; split2b(v, h, l);
        size_t o = (size_t)(bx + i) * CH + by + tx;
        hi[o] = *reinterpret_cast<u16*>(&h);
        lo[o] = *reinterpret_cast<u16*>(&l);
    }
}

// transpose 768x768 weight, fp16 single
__global__ __launch_bounds__(256) void wt_fp(const float* __restrict__ W,
                                             u16* __restrict__ f) {
    __shared__ float t[32][33];
    int bx = blockIdx.x * 32, by = blockIdx.y * 32;
    int tx = threadIdx.x & 31, ty = threadIdx.x >> 5;
#pragma unroll
    for (int i = ty; i < 32; i += 8)
        t[i][tx] = W[(size_t)(by + i) * CH + bx + tx];
    __syncthreads();
#pragma unroll
    for (int i = ty; i < 32; i += 8) {
        __half h = __float2half_rn(t[tx][i]);
        f[(size_t)(bx + i) * CH + by + tx] = *reinterpret_cast<u16*>(&h);
    }
}

// ---------------------------------------------------------------------------
// Block reductions / softmax / ratios / xs / layernorm
// ---------------------------------------------------------------------------
__device__ __forceinline__ float blk_red(float v, bool is_max) {
    __shared__ float red[8];
    int lane = threadIdx.x & 31, w = threadIdx.x >> 5;
#pragma unroll
    for (int o = 16; o; o >>= 1) {
        float u = __shfl_xor_sync(0xffffffffu, v, o);
        v = is_max ? fmaxf(v, u) : v + u;
    }
    if (lane == 0) red[w] = v;
    __syncthreads();
    if (w == 0) {
        v = (lane < 8) ? red[lane] : (is_max ? -3.4e38f : 0.f);
#pragma unroll
        for (int o = 4; o; o >>= 1) {
            float u = __shfl_xor_sync(0xffffffffu, v, o);
            v = is_max ? fmaxf(v, u) : v + u;
        }
        if (lane == 0) red[0] = v;
    }
    __syncthreads();
    v = red[0];
    __syncthreads();
    return v;
}

// softmax: fp32 probs in place + fp16 probs (for 1-pass PV)
__global__ __launch_bounds__(256) void softmax_kernel(float* __restrict__ S,
                                                      u16* __restrict__ f) {
    size_t base = (size_t)blockIdx.x * NS;
    __shared__ float buf[NS];
    int tid = threadIdx.x;
    float m = -3.4e38f;
    for (int c = tid; c < NS; c += 256) { float v = S[base + c]; buf[c] = v; m = fmaxf(m, v); }
    m = blk_red(m, true);
    float s = 0.f;
    for (int c = tid; c < NS; c += 256) { float e = __expf(buf[c] - m); buf[c] = e; s += e; }
    s = blk_red(s, false);
    float inv = 1.f / s;
    for (int c = tid; c < NS; c += 256) {
        float p = buf[c] * inv;
        S[base + c] = p;
        __half hp = __float2half_rn(p);
        f[base + c] = *reinterpret_cast<u16*>(&hp);
    }
}

// Coalesced sign-count ratios
__global__ __launch_bounds__(128) void ratio_kernel(const float* __restrict__ S,
                                                    const float* __restrict__ Si,
                                                    float* __restrict__ s1,
                                                    float* __restrict__ s2) {
    int b = blockIdx.y;
    int n = blockIdx.x * 128 + threadIdx.x;
    if (n >= NS) return;
    const float* a  = S  + (size_t)b * NT * NS;
    const float* ai = Si + (size_t)b * NT * NS;
    int pos = 0, eq = 0;
#pragma unroll 4
    for (int t = 0; t < NT; t++) {
        float x = a[(size_t)t * NS + n], y = ai[(size_t)t * NS + n];
        pos += (x > y);
        eq  += (x == y);
    }
    float rgb = pos * (1.f / NT), eqr = eq * (1.f / NT);
    int idx = b * NS + n;
    s1[idx] = rgb + eqr;
    s2[idx] = 1.f - rgb;
}

// x_s[key][c] = s1[key]*v[key][c] + s2[key]*vi[key][c], v from fp16 VT (transposed)
__global__ __launch_bounds__(256) void xs_kernel(const u16* __restrict__ VT,
                                                 const u16* __restrict__ VIT,
                                                 const float* __restrict__ s1,
                                                 const float* __restrict__ s2,
                                                 float* __restrict__ out) {
    __shared__ float tv[32][33], tw[32][33];
    int k0 = blockIdx.x * 32, c0 = blockIdx.y * 32;
    int tx = threadIdx.x & 31, ty = threadIdx.x >> 5;
#pragma unroll
    for (int i = ty; i < 32; i += 8) {
        size_t o = (size_t)(c0 + i) * MK + k0 + tx;
        tv[i][tx] = __half2float(*reinterpret_cast<const __half*>(VT + o));
        tw[i][tx] = __half2float(*reinterpret_cast<const __half*>(VIT + o));
    }
    __syncthreads();
#pragma unroll
    for (int i = ty; i < 32; i += 8) {
        int key = k0 + i;
        float a = s1[key], b = s2[key];
        out[(size_t)key * CH + c0 + tx] = a * tv[tx][i] + b * tw[tx][i];
    }
}

__global__ __launch_bounds__(256) void ln_kernel(const float* __restrict__ U,
                                                 const float* __restrict__ gamma,
                                                 const float* __restrict__ beta,
                                                 float* __restrict__ out) {
    size_t base = (size_t)blockIdx.x * CH;
    __shared__ float buf[CH];
    int tid = threadIdx.x;
    float s = 0.f;
    for (int c = tid; c < CH; c += 256) { float v = U[base + c]; buf[c] = v; s += v; }
    s = blk_red(s, false);
    float mu = s * (1.f / CH);
    float vs = 0.f;
    for (int c = tid; c < CH; c += 256) { float d = buf[c] - mu; vs += d * d; }
    vs = blk_red(vs, false);
    float inv = rsqrtf(vs * (1.f / CH) + 1e-5f);
    for (int c = tid; c < CH; c += 256)
        out[base + c] = (buf[c] - mu) * inv * gamma[c] + beta[c];
}

// ---------------------------------------------------------------------------
// Launcher. ncu captures the 4th launch (0-based index 3): K/KI bf16 3-pass.
// ---------------------------------------------------------------------------
extern "C" void kernel_launch(void* const* d_in, const int* in_sizes, int n_in,
                              void* d_out, int out_size) {
    const float* T     = (const float*)d_in[0];
    const float* x     = (const float*)d_in[1];
    const float* xi    = (const float*)d_in[2];
    const float* Wq    = (const float*)d_in[3];
    const float* Wk    = (const float*)d_in[4];
    const float* Wv    = (const float*)d_in[5];
    const float* Wout  = (const float*)d_in[6];
    const float* gamma = (const float*)d_in[7];
    const float* beta  = (const float*)d_in[8];
    float* out = (float*)d_out;

    void* up = nullptr; cudaGetSymbolAddress(&up, g_u);
    void* fp = nullptr; cudaGetSymbolAddress(&fp, g_f);
    u16*   U = (u16*)up;
    float* F = (float*)fp;

    // sign path (bf16 3-pass)
    cudaFuncSetAttribute(gemm_mma<1, false, false, false, 3, false>, cudaFuncAttributeMaxDynamicSharedMemorySize, SMEM_REQ);
    cudaFuncSetAttribute(gemm_mma<0, false, false, true,  3, false>, cudaFuncAttributeMaxDynamicSharedMemorySize, SMEM_REQ);
    // value path (fp16 1-pass)
    cudaFuncSetAttribute(gemm_mma<2, false, false, false, 1, true>,  cudaFuncAttributeMaxDynamicSharedMemorySize, SMEM_REQ);
    cudaFuncSetAttribute(gemm_mma<2, false, true,  false, 1, true>,  cudaFuncAttributeMaxDynamicSharedMemorySize, SMEM_REQ);
    cudaFuncSetAttribute(gemm_mma<0, true,  false, false, 1, true>,  cudaFuncAttributeMaxDynamicSharedMemorySize, SMEM_REQ);

    const float scale = 1.0f / sqrtf((float)CH);
    auto grid = [](int M, int N, int Z) {
        return dim3((unsigned)((N + 63) / 64), (unsigned)((M + 127) / 128), (unsigned)Z);
    };
    dim3 wt_g(CH / 32, CH / 32);

    // --- launches 1-3: minimal deps for the profiled GEMM ---
    wt_bf<<<wt_g, 256>>>(Wk, U + O_WK, U + O_WK + SZ_W);                              // 1
    cvt_gather3<<<(unsigned)(SZ_X / 4 / 256), 256>>>(x,  U + O_XS,  U + O_XS  + SZ_X, U + O_XSF);  // 2
    cvt_gather3<<<(unsigned)(SZ_X / 4 / 256), 256>>>(xi, U + O_XIS, U + O_XIS + SZ_X, U + O_XISF); // 3

    // --- launch 4 (PROFILED): K + KI projections (bf16 3-pass, z=2) ---
    gemm_mma<1, false, false, false, 3, false><<<grid(MK, CH, 2), 256, SMEM_REQ>>>(
        U + O_XS, U + O_XS + SZ_X, U + O_WK, U + O_WK + SZ_W,
        nullptr, nullptr, nullptr, nullptr,
        nullptr, U + O_K, U + O_K + SZ_X, nullptr,
        MK, CH, CH, 0, CH, CH, CH,
        (long long)(2 * SZ_X), 0, (long long)(2 * SZ_X), 0, 0, 1.f);

    // remaining converts + weight transposes
    wt_bf<<<wt_g, 256>>>(Wq, U + O_WQ, U + O_WQ + SZ_W);
    wt_fp<<<wt_g, 256>>>(Wv,   U + O_WVF);
    wt_fp<<<wt_g, 256>>>(Wout, U + O_WOF);
    cvt_split<<<(unsigned)(SZ_T / 4 / 256), 256>>>(T, U + O_T, U + O_T + SZ_T, SZ_T / 4);

    // Q = T @ Wq (bf16 3-pass, split out)
    gemm_mma<1, false, false, false, 3, false><<<grid(MQ, CH, 1), 256, SMEM_REQ>>>(
        U + O_T, U + O_T + SZ_T, U + O_WQ, U + O_WQ + SZ_W,
        nullptr, nullptr, nullptr, nullptr,
        nullptr, U + O_Q, U + O_Q + SZ_T, nullptr,
        MQ, CH, CH, 0, CH, CH, CH, 0, 0, 0, 0, 0, 1.f);

    // VT / VIT (fp16 1-pass, z=2): VT[c][key] = sum_k WvT[c,k]*xs[key,k]
    gemm_mma<2, false, false, false, 1, true><<<grid(CH, MK, 2), 256, SMEM_REQ>>>(
        U + O_WVF, nullptr, U + O_XSF, nullptr,
        nullptr, nullptr, nullptr, nullptr,
        nullptr, U + O_VT, nullptr, nullptr,
        CH, MK, CH, 0, CH, CH, MK,
        0, (long long)SZ_X, (long long)SZ_X, 0, 0, 1.f);

    // logits (bf16 3-pass): z in [0,64), zz=z&31 batch, z>=32 -> KI/SI
    gemm_mma<0, false, false, true, 3, false><<<grid(NT, NS, 64), 256, SMEM_REQ>>>(
        U + O_Q, U + O_Q + SZ_T, U + O_K, U + O_K + SZ_X,
        nullptr, nullptr, nullptr, nullptr,
        F + F_S, nullptr, nullptr, nullptr,
        NT, NS, CH, 0, CH, CH, NS,
        (long long)NT * CH, (long long)NS * CH, (long long)NT * NS,
        (long long)(2 * SZ_X), (long long)SZ_S, scale);

    // softmax: fp32 probs in place + fp16 probs
    softmax_kernel<<<MQ, 256>>>(F + F_S,  U + O_SHF);
    softmax_kernel<<<MQ, 256>>>(F + F_SI, U + O_SIHF);

    // ratios (coalesced) + x_s
    ratio_kernel<<<dim3((NS + 127) / 128, BATCH), 128>>>(F + F_S, F + F_SI, F + F_S1, F + F_S2);
    xs_kernel<<<dim3(MK / 32, CH / 32), 256>>>(
        U + O_VT, U + O_VIT, F + F_S1, F + F_S2, out);

    // P = aw @ v + awi @ vi (fp16 DUAL 1-pass, fp16 out)
    gemm_mma<2, false, true, false, 1, true><<<grid(NT, CH, BATCH), 256, SMEM_REQ>>>(
        U + O_SHF,  nullptr, U + O_VT,  nullptr,
        U + O_SIHF, nullptr, U + O_VIT, nullptr,
        nullptr, U + O_PF, nullptr, nullptr,
        NT, CH, NS, NS, NS, MK, CH,
        (long long)NT * NS, (long long)NS, (long long)NT * CH, 0, 0, 1.f);

    // U = P @ Wout + T (fp16 1-pass, fp32 out + T)
    gemm_mma<0, true, false, false, 1, true><<<grid(MQ, CH, 1), 256, SMEM_REQ>>>(
        U + O_PF, nullptr, U + O_WOF, nullptr,
        nullptr, nullptr, nullptr, nullptr,
        F + F_U, nullptr, nullptr, T,
        MQ, CH, CH, 0, CH, CH, CH, 0, 0, 0, 0, 0, 1.f);

    // T_new = LayerNorm(U)
    ln_kernel<<<MQ, 256>>>(F + F_U, gamma, beta, out + SZ_X);
}